// round 12
// baseline (speedup 1.0000x reference)
#include <cuda_runtime.h>
#include <cuda_bf16.h>

// QuantumLayer analytic collapse:
//   out[b,i] = prod_{c <= i, ((i-c) & (L-1)) == 0} cos(x[b,c])
// Derivation: RZ layers are unit-modulus diagonal phases -> cancel in |.|^2;
// the CNOT chain is the GF(2) prefix-sum matrix M; Z_i after L layers pulls
// back to the parity set = row i of M^L, (M^L)_{ic} = C(i-c+L-1, L-1) mod 2,
// odd iff ((i-c) & (L-1)) == 0 (Kummer). The initial state is a product
// measure, so the parity expectation factorizes into prod cos(x_c).
// q_weights is mathematically irrelevant to the output.
//
// Perf conclusions (R1-R11, FINAL): kernel time is pinned at ~4.0-4.45us for
// every implementation tried (smem-staged, row/thread, pair/thread,
// elem/thread, 2x redundant) — launch overhead + one memory round trip;
// DRAM 0.5%, all pipes <1%. Byte-identical source measured 4.58/4.93/5.86us
// wall across runs -> +-0.5us variance band; grids < 148 blocks
// pathologically inflate wall time (low-grid clock throttle). This config
// (160 blocks x 256 threads, one thread per element) is the measured best
// and the converged final answer.

constexpr int N = 10;   // wires (q_weights.shape[1])

// Specialized: power-of-2 L -> membership is stride-L. One thread per output
// element; <=ceil(N/L) independent predicated loads + MUFU cos, no sync.
template<int L>
__global__ __launch_bounds__(256)
void quantum_elem_kernel(const float* __restrict__ x,
                         float* __restrict__ out, int total) {
    int t = blockIdx.x * blockDim.x + threadIdx.x;
    if (t >= total) return;
    int b = t / N;            // constexpr divisor -> mul/shift, no IDIV
    int i = t - b * N;
    const float* row = x + b * N;

    float p = __cosf(__ldg(row + i));
    #pragma unroll
    for (int k = 1; k * L < N; k++) {
        int c = i - k * L;
        if (c >= 0) p *= __cosf(__ldg(row + c));
    }
    out[t] = p;
}

// Generic fallback: any L, Kummer mask rule.
__global__ __launch_bounds__(256)
void quantum_generic_kernel(const float* __restrict__ x,
                            float* __restrict__ out,
                            int total, int Lm1) {
    int t = blockIdx.x * blockDim.x + threadIdx.x;
    if (t >= total) return;
    int b = t / N;
    int i = t - b * N;
    const float* row = x + b * N;
    float p = 1.0f;
    #pragma unroll
    for (int c = i; c >= 0; --c)
        if (((i - c) & Lm1) == 0)
            p *= __cosf(__ldg(row + c));
    out[t] = p;
}

extern "C" void kernel_launch(void* const* d_in, const int* in_sizes, int n_in,
                              void* d_out, int out_size) {
    const float* x = (const float*)d_in[0];
    // d_in[1] = q_weights: unused (phases cancel in probabilities)
    const int L = in_sizes[1] / N;   // layers
    const int total = out_size;      // B * N
    float* out = (float*)d_out;

    const int threads = 256;
    const int blocks = (total + threads - 1) / threads;

    switch (L) {
        case 1: quantum_elem_kernel<1><<<blocks, threads>>>(x, out, total); break;
        case 2: quantum_elem_kernel<2><<<blocks, threads>>>(x, out, total); break;
        case 4: quantum_elem_kernel<4><<<blocks, threads>>>(x, out, total); break;
        case 8: quantum_elem_kernel<8><<<blocks, threads>>>(x, out, total); break;
        default:
            quantum_generic_kernel<<<blocks, threads>>>(x, out, total, L - 1);
    }
}

// round 13
// speedup vs baseline: 1.1146x; 1.1146x over previous
#include <cuda_runtime.h>
#include <cuda_bf16.h>

// QuantumLayer analytic collapse:
//   out[b,i] = prod_{c <= i, ((i-c) & (L-1)) == 0} cos(x[b,c])
// Derivation: RZ layers are unit-modulus diagonal phases -> cancel in |.|^2;
// the CNOT chain is the GF(2) prefix-sum matrix M; Z_i after L layers pulls
// back to the parity set = row i of M^L, (M^L)_{ic} = C(i-c+L-1, L-1) mod 2,
// odd iff ((i-c) & (L-1)) == 0 (Kummer). The initial state is a product
// measure, so the parity expectation factorizes into prod cos(x_c).
// q_weights is mathematically irrelevant to the output.
//
// Perf conclusions (R1-R12, FINAL): kernel time is pinned at 3.97-4.45us for
// every implementation tried (smem-staged, row/thread, pair/thread,
// elem/thread, 2x redundant) — launch overhead + one memory round trip;
// DRAM 0.5%, all pipes <1%. Byte-identical source measured 4.58/4.93/5.86/
// 6.85us wall across four runs -> the wall-clock spread is measurement
// noise, not kernel behavior. Grids < 148 blocks pathologically inflate
// wall time (low-grid clock throttle). This config (160 blocks x 256
// threads, one thread per element) holds the session-best 4.58us and the
// best kernel-time floor; it is the converged final answer.

constexpr int N = 10;   // wires (q_weights.shape[1])

// Specialized: power-of-2 L -> membership is stride-L. One thread per output
// element; <=ceil(N/L) independent predicated loads + MUFU cos, no sync.
template<int L>
__global__ __launch_bounds__(256)
void quantum_elem_kernel(const float* __restrict__ x,
                         float* __restrict__ out, int total) {
    int t = blockIdx.x * blockDim.x + threadIdx.x;
    if (t >= total) return;
    int b = t / N;            // constexpr divisor -> mul/shift, no IDIV
    int i = t - b * N;
    const float* row = x + b * N;

    float p = __cosf(__ldg(row + i));
    #pragma unroll
    for (int k = 1; k * L < N; k++) {
        int c = i - k * L;
        if (c >= 0) p *= __cosf(__ldg(row + c));
    }
    out[t] = p;
}

// Generic fallback: any L, Kummer mask rule.
__global__ __launch_bounds__(256)
void quantum_generic_kernel(const float* __restrict__ x,
                            float* __restrict__ out,
                            int total, int Lm1) {
    int t = blockIdx.x * blockDim.x + threadIdx.x;
    if (t >= total) return;
    int b = t / N;
    int i = t - b * N;
    const float* row = x + b * N;
    float p = 1.0f;
    #pragma unroll
    for (int c = i; c >= 0; --c)
        if (((i - c) & Lm1) == 0)
            p *= __cosf(__ldg(row + c));
    out[t] = p;
}

extern "C" void kernel_launch(void* const* d_in, const int* in_sizes, int n_in,
                              void* d_out, int out_size) {
    const float* x = (const float*)d_in[0];
    // d_in[1] = q_weights: unused (phases cancel in probabilities)
    const int L = in_sizes[1] / N;   // layers
    const int total = out_size;      // B * N
    float* out = (float*)d_out;

    const int threads = 256;
    const int blocks = (total + threads - 1) / threads;

    switch (L) {
        case 1: quantum_elem_kernel<1><<<blocks, threads>>>(x, out, total); break;
        case 2: quantum_elem_kernel<2><<<blocks, threads>>>(x, out, total); break;
        case 4: quantum_elem_kernel<4><<<blocks, threads>>>(x, out, total); break;
        case 8: quantum_elem_kernel<8><<<blocks, threads>>>(x, out, total); break;
        default:
            quantum_generic_kernel<<<blocks, threads>>>(x, out, total, L - 1);
    }
}

// round 14
// speedup vs baseline: 1.5177x; 1.3617x over previous
#include <cuda_runtime.h>
#include <cuda_bf16.h>

// QuantumLayer analytic collapse:
//   out[b,i] = prod_{c <= i, ((i-c) & (L-1)) == 0} cos(x[b,c])
// Derivation: RZ layers are unit-modulus diagonal phases -> cancel in |.|^2;
// the CNOT chain is the GF(2) prefix-sum matrix M; Z_i after L layers pulls
// back to the parity set = row i of M^L, (M^L)_{ic} = C(i-c+L-1, L-1) mod 2,
// odd iff ((i-c) & (L-1)) == 0 (Kummer). The initial state is a product
// measure, so the parity expectation factorizes into prod cos(x_c).
// q_weights is mathematically irrelevant to the output.
//
// Perf conclusions (R1-R13, FINAL): kernel time is pinned at 3.97-4.54us for
// every implementation tried (smem-staged, row/thread, pair/thread,
// elem/thread, 2x redundant) — launch overhead + one memory round trip;
// DRAM 0.5%, all pipes <1%, issue ~6%. Byte-identical source measured
// 4.58/4.93/5.86/6.85/6.14us wall across five runs: the wall-clock spread is
// measurement noise (shared GPU / replay loop), not kernel behavior. Grids
// < 148 blocks pathologically inflate wall time (low-grid clock throttle).
// This config (160 blocks x 256 threads, one thread per element) holds the
// session-best 4.58us and the best kernel-time floor; converged final answer.

constexpr int N = 10;   // wires (q_weights.shape[1])

// Specialized: power-of-2 L -> membership is stride-L. One thread per output
// element; <=ceil(N/L) independent predicated loads + MUFU cos, no sync.
template<int L>
__global__ __launch_bounds__(256)
void quantum_elem_kernel(const float* __restrict__ x,
                         float* __restrict__ out, int total) {
    int t = blockIdx.x * blockDim.x + threadIdx.x;
    if (t >= total) return;
    int b = t / N;            // constexpr divisor -> mul/shift, no IDIV
    int i = t - b * N;
    const float* row = x + b * N;

    float p = __cosf(__ldg(row + i));
    #pragma unroll
    for (int k = 1; k * L < N; k++) {
        int c = i - k * L;
        if (c >= 0) p *= __cosf(__ldg(row + c));
    }
    out[t] = p;
}

// Generic fallback: any L, Kummer mask rule.
__global__ __launch_bounds__(256)
void quantum_generic_kernel(const float* __restrict__ x,
                            float* __restrict__ out,
                            int total, int Lm1) {
    int t = blockIdx.x * blockDim.x + threadIdx.x;
    if (t >= total) return;
    int b = t / N;
    int i = t - b * N;
    const float* row = x + b * N;
    float p = 1.0f;
    #pragma unroll
    for (int c = i; c >= 0; --c)
        if (((i - c) & Lm1) == 0)
            p *= __cosf(__ldg(row + c));
    out[t] = p;
}

extern "C" void kernel_launch(void* const* d_in, const int* in_sizes, int n_in,
                              void* d_out, int out_size) {
    const float* x = (const float*)d_in[0];
    // d_in[1] = q_weights: unused (phases cancel in probabilities)
    const int L = in_sizes[1] / N;   // layers
    const int total = out_size;      // B * N
    float* out = (float*)d_out;

    const int threads = 256;
    const int blocks = (total + threads - 1) / threads;

    switch (L) {
        case 1: quantum_elem_kernel<1><<<blocks, threads>>>(x, out, total); break;
        case 2: quantum_elem_kernel<2><<<blocks, threads>>>(x, out, total); break;
        case 4: quantum_elem_kernel<4><<<blocks, threads>>>(x, out, total); break;
        case 8: quantum_elem_kernel<8><<<blocks, threads>>>(x, out, total); break;
        default:
            quantum_generic_kernel<<<blocks, threads>>>(x, out, total, L - 1);
    }
}